// round 5
// baseline (speedup 1.0000x reference)
#include <cuda_runtime.h>
#include <cuda_bf16.h>
#include <cstdint>

// ---------------------------------------------------------------------------
// Problem constants
// ---------------------------------------------------------------------------
#define BSZ    4096
#define ITEMW  10242
#define KTOT   10368      // padded GEMM K: 64 (genre) + 2240 (director) + 8064 (actor)
#define NCH    162        // KTOT / 64 chunks
#define CPS    41         // chunks per K-split (last split has 39)
#define NSPLIT 4
#define PCOLS  216        // 3 fields x 72 partial columns (64 num + count@64 + 7 pad)

// Field chunk ranges: genre [0,1), director [1,36), actor [36,162)

// ---------------------------------------------------------------------------
// Device scratch (static globals; no allocations anywhere)
// ---------------------------------------------------------------------------
__device__ __align__(16) __nv_bfloat16 g_WT[65 * KTOT];     // fused weights, row d, k-contiguous; row 64 = validity
__device__ float g_UF[3528 * 64];                            // user folds: gender@0, age@98, occ@105, area@126
__device__ float g_RF[6 * 64];                               // rate_tab @ item_W[0:64]
__device__ float g_part[(size_t)NSPLIT * BSZ * PCOLS];       // GEMM partials
__device__ float g_X[BSZ * 64], g_Y[BSZ * 64];               // x, y vectors
__device__ float g_S[BSZ * 8];                               // per-row scalars (6 used)
__device__ float g_SP[4 * 1024 * 64];                        // per-CTA partials of s1..s4
__device__ float g_U[4 * 64];                                // u1..u4
__device__ float g_O3[64];                                   // edge-branch output row

// ---------------------------------------------------------------------------
// K0a: fold item-side weights into g_WT (bf16) + validity row
// ---------------------------------------------------------------------------
__global__ void k0_wt(const float* __restrict__ genre_W, const float* __restrict__ director_W,
                      const float* __restrict__ actor_W, const float* __restrict__ item_W)
{
    int k = blockIdx.x;          // padded k, 0..KTOT-1
    int d = threadIdx.x;         // 0..63
    int kr, len, iwo;
    const float* W;
    if (k < 64)        { kr = k;        len = 25;   W = genre_W;    iwo = 64;  }
    else if (k < 2304) { kr = k - 64;   len = 2186; W = director_W; iwo = 128; }
    else               { kr = k - 2304; len = 8030; W = actor_W;    iwo = 192; }
    float v = 0.f;
    if (kr < len) {
        #pragma unroll 8
        for (int j = 0; j < 64; ++j)
            v += W[kr * 64 + j] * item_W[(iwo + j) * 64 + d];
    }
    g_WT[(size_t)d * KTOT + k] = __float2bfloat16(v);
    if (d == 0)
        g_WT[(size_t)64 * KTOT + k] = __float2bfloat16(kr < len ? 1.f : 0.f);
}

// ---------------------------------------------------------------------------
// K0b: fold user-side tables and rate table
// ---------------------------------------------------------------------------
__global__ void k0_user(const float* __restrict__ gender_tab, const float* __restrict__ age_tab,
                        const float* __restrict__ occ_tab, const float* __restrict__ area_tab,
                        const float* __restrict__ user_W, const float* __restrict__ rate_tab,
                        const float* __restrict__ item_W)
{
    int r = blockIdx.x;          // 0..3533
    int d = threadIdx.x;         // 0..63
    const float* tab; const float* W; float* outp;
    if (r < 98)        { tab = gender_tab + r * 64;        W = user_W;            outp = g_UF + r * 64; }
    else if (r < 105)  { tab = age_tab + (r - 98) * 64;    W = user_W + 64 * 64;  outp = g_UF + r * 64; }
    else if (r < 126)  { tab = occ_tab + (r - 105) * 64;   W = user_W + 128 * 64; outp = g_UF + r * 64; }
    else if (r < 3528) { tab = area_tab + (r - 126) * 64;  W = user_W + 192 * 64; outp = g_UF + r * 64; }
    else               { tab = rate_tab + (r - 3528) * 64; W = item_W;            outp = g_RF + (r - 3528) * 64; }
    float v = 0.f;
    #pragma unroll 8
    for (int j = 0; j < 64; ++j)
        v += tab[j] * W[j * 64 + d];
    outp[d] = v;
}

// ---------------------------------------------------------------------------
// K1: the HBM-bound bits GEMM
//   A[64 rows][64 k] bf16 tile (bits), B = WT tile (65 rows d + count/validity)
//   Warp layout: 8 warps = 4 m-tiles x 2 n-groups; n-group 0 -> local n-tiles
//   {0,2,4,6,8}, group 1 -> {1,3,5,7}. Accumulators static per field.
// ---------------------------------------------------------------------------
#define ASTR 144   // smem row stride in bytes (64 bf16 + 8 pad)

template<int COL0, int LEN, int KR0>
__device__ __forceinline__ void gemm_chunk(
    const int* __restrict__ item, int rt, int chunk,
    uint8_t* As, uint8_t* Ms, int tid, int lane, int wm, int wg,
    float (&acc)[5][4])
{
    __syncthreads();   // protect smem from previous chunk's consumers
    const int kbase = chunk * 64;
    const int krb = kbase - KR0;

    // ---- A tile: 64 rows x 64 k, coalesced int loads -> bf16x2 smem stores
    #pragma unroll
    for (int it = 0; it < 8; ++it) {
        int idx2 = it * 512 + tid * 2;      // element pair index in [0,4096)
        int row = idx2 >> 6;
        int kk  = idx2 & 63;
        int kr  = krb + kk;
        const int* p = item + (long)(rt * 64 + row) * ITEMW + COL0 + kr;
        float f0 = (kr < LEN)     ? (float)p[0] : 0.f;
        float f1 = (kr + 1 < LEN) ? (float)p[1] : 0.f;
        __nv_bfloat162 h = __floats2bfloat162_rn(f0, f1);
        *(uint32_t*)(As + row * ASTR + kk * 2) = *(uint32_t*)&h;
    }

    // ---- WT tile: 65 rows x 64 k (bf16), k-contiguous from L2
    #pragma unroll
    for (int it = 0; it < 9; ++it) {
        int j = it * 256 + tid;
        if (j < 65 * 32) {
            int dd = j >> 5, w = j & 31;
            uint32_t v = *(const uint32_t*)&g_WT[(size_t)dd * KTOT + kbase + 2 * w];
            *(uint32_t*)(Ms + dd * ASTR + w * 4) = v;
        }
    }
    __syncthreads();

    // ---- MMA: 4 k-steps of m16n8k16
    #pragma unroll
    for (int ks = 0; ks < 4; ++ks) {
        int ac = ks * 16 + 2 * (lane & 3);
        int ar = wm * 16 + (lane >> 2);
        uint32_t a0 = *(uint32_t*)(As + ar * ASTR + ac * 2);
        uint32_t a1 = *(uint32_t*)(As + (ar + 8) * ASTR + ac * 2);
        uint32_t a2 = *(uint32_t*)(As + ar * ASTR + (ac + 8) * 2);
        uint32_t a3 = *(uint32_t*)(As + (ar + 8) * ASTR + (ac + 8) * 2);
        #pragma unroll
        for (int li = 0; li < 5; ++li) {
            int l = wg + 2 * li;
            if (l < 9) {
                int br = l * 8 + (lane >> 2);
                uint32_t b0 = *(uint32_t*)(Ms + br * ASTR + ac * 2);
                uint32_t b1 = *(uint32_t*)(Ms + br * ASTR + (ac + 8) * 2);
                asm volatile(
                    "mma.sync.aligned.m16n8k16.row.col.f32.bf16.bf16.f32 "
                    "{%0,%1,%2,%3}, {%4,%5,%6,%7}, {%8,%9}, {%0,%1,%2,%3};\n"
                    : "+f"(acc[li][0]), "+f"(acc[li][1]), "+f"(acc[li][2]), "+f"(acc[li][3])
                    : "r"(a0), "r"(a1), "r"(a2), "r"(a3), "r"(b0), "r"(b1));
            }
        }
    }
}

__global__ void __launch_bounds__(256, 2) k1_gemm(const int* __restrict__ item)
{
    __shared__ __align__(16) uint8_t As[64 * ASTR];
    __shared__ __align__(16) uint8_t Ms[72 * ASTR];
    int tid = threadIdx.x, lane = tid & 31, warp = tid >> 5;
    int wm = warp & 3, wg = warp >> 2;
    int rt = blockIdx.x;   // 0..63 row tiles
    int sp = blockIdx.y;   // 0..3 k-splits

    // zero the pad rows 65..71 of the WT tile once (never rewritten)
    if (tid < 252) *(uint32_t*)(Ms + 65 * ASTR + tid * 4) = 0u;

    float acc0[5][4] = {}, acc1[5][4] = {}, acc2[5][4] = {};
    int c0 = sp * CPS, c1 = min(NCH, c0 + CPS);

    for (int c = c0; c < min(c1, 1); ++c)
        gemm_chunk<1, 25, 0>(item, rt, c, As, Ms, tid, lane, wm, wg, acc0);
    for (int c = max(c0, 1); c < min(c1, 36); ++c)
        gemm_chunk<26, 2186, 64>(item, rt, c, As, Ms, tid, lane, wm, wg, acc1);
    for (int c = max(c0, 36); c < c1; ++c)
        gemm_chunk<2212, 8030, 2304>(item, rt, c, As, Ms, tid, lane, wm, wg, acc2);

    // flush all 3 field blocks (untouched ones write zeros -> no scratch memset)
    float* base = g_part + (size_t)sp * BSZ * PCOLS;
    int row = rt * 64 + wm * 16 + (lane >> 2);
    int tg2 = 2 * (lane & 3);

#define FLUSH(F, A)                                                     \
    _Pragma("unroll")                                                   \
    for (int li = 0; li < 5; ++li) {                                    \
        int l = wg + 2 * li;                                            \
        if (l < 9) {                                                    \
            int col = (F) * 72 + l * 8 + tg2;                           \
            base[(size_t)row * PCOLS + col]           = A[li][0];       \
            base[(size_t)row * PCOLS + col + 1]       = A[li][1];       \
            base[(size_t)(row + 8) * PCOLS + col]     = A[li][2];       \
            base[(size_t)(row + 8) * PCOLS + col + 1] = A[li][3];       \
        }                                                               \
    }
    FLUSH(0, acc0)
    FLUSH(1, acc1)
    FLUSH(2, acc2)
#undef FLUSH
}

// ---------------------------------------------------------------------------
// K2: reduce splits, finalize x / y / edge, per-row scalars, s-vector partials
//   4 rows per CTA, 64 threads (one per d) per row.
// ---------------------------------------------------------------------------
__global__ void __launch_bounds__(256) k2_finalize(
    const int* __restrict__ user_emb, const int* __restrict__ item,
    const int* __restrict__ edge_emb,
    const float* __restrict__ user_b, const float* __restrict__ item_b,
    const float* __restrict__ edges_tab,
    const float* __restrict__ uu_w, const float* __restrict__ ui_w,
    const float* __restrict__ iu_w, const float* __restrict__ ii_w)
{
    int tid = threadIdx.x, lane = tid & 31, warp = tid >> 5;
    int rr = tid >> 6, d = tid & 63;
    int row = blockIdx.x * 4 + rr;

    float ng = 0, cg = 0, nd = 0, cd = 0, na = 0, ca = 0;
    #pragma unroll
    for (int s = 0; s < NSPLIT; ++s) {
        const float* p = g_part + ((size_t)s * BSZ + row) * PCOLS;
        ng += p[d];        cg += p[64];
        nd += p[72 + d];   cd += p[72 + 64];
        na += p[144 + d];  ca += p[144 + 64];
    }
    int ri = item[(long)row * ITEMW];
    float y = (g_RF[ri * 64 + d] + ng / cg + nd / cd + na / ca + item_b[d]) * 0.12f;

    int gi = user_emb[row * 4 + 0], ai = user_emb[row * 4 + 1];
    int oi = user_emb[row * 4 + 2], ari = user_emb[row * 4 + 3];
    float x = (g_UF[gi * 64 + d] + g_UF[(98 + ai) * 64 + d] + g_UF[(105 + oi) * 64 + d]
             + g_UF[(126 + ari) * 64 + d] + user_b[d]) * 0.12f;
    float e = edges_tab[edge_emb[row] * 64 + d] * 0.12f;

    g_X[row * 64 + d] = x;
    g_Y[row * 64 + d] = y;

    __shared__ float sx[4][64], sy[4][64];
    __shared__ float red[8][6], srow[4][6];
    sx[rr][d] = x; sy[rr][d] = y;

    float xe = x * e, ye = y * e;
    float pr[6] = { xe * uu_w[d], xe * ui_w[d], ye * ui_w[d],
                    ye * ii_w[d], ye * iu_w[d], xe * iu_w[d] };
    #pragma unroll
    for (int o = 16; o; o >>= 1) {
        #pragma unroll
        for (int j = 0; j < 6; ++j) pr[j] += __shfl_xor_sync(0xffffffffu, pr[j], o);
    }
    if (lane == 0) {
        #pragma unroll
        for (int j = 0; j < 6; ++j) red[warp][j] = pr[j];
    }
    __syncthreads();
    if (tid < 24) {
        int r2 = tid / 6, j = tid % 6;
        float v = red[2 * r2][j] + red[2 * r2 + 1][j];
        srow[r2][j] = v;
        g_S[(size_t)(blockIdx.x * 4 + r2) * 8 + j] = v;
    }
    __syncthreads();
    if (tid < 64) {
        float s1 = 0, s2 = 0, s3 = 0, s4 = 0;
        #pragma unroll
        for (int r2 = 0; r2 < 4; ++r2) {
            float xv = sx[r2][tid], yv = sy[r2][tid];
            s1 += srow[r2][0] * xv;   // x_xx * x
            s2 += srow[r2][2] * yv;   // x_xy_y * y
            s3 += srow[r2][3] * yv;   // y_yy * y
            s4 += srow[r2][5] * xv;   // y_yx_x * x
        }
        g_SP[(0 * 1024 + blockIdx.x) * 64 + tid] = s1;
        g_SP[(1 * 1024 + blockIdx.x) * 64 + tid] = s2;
        g_SP[(2 * 1024 + blockIdx.x) * 64 + tid] = s3;
        g_SP[(3 * 1024 + blockIdx.x) * 64 + tid] = s4;
    }
}

// ---------------------------------------------------------------------------
// K3: reduce s-vectors over 1024 CTA partials, compute u1..u4 and edge branch
// ---------------------------------------------------------------------------
__global__ void __launch_bounds__(1024) k3_reduce(
    const float* __restrict__ uu_W1, const float* __restrict__ ui_W1,
    const float* __restrict__ ii_W1, const float* __restrict__ iu_W1,
    const float* __restrict__ edge_W, const float* __restrict__ edges_tab)
{
    int tid = threadIdx.x;
    int q = tid >> 8, v = (tid >> 6) & 3, d = tid & 63;
    float s = 0.f;
    #pragma unroll 8
    for (int i = q * 256; i < q * 256 + 256; ++i)
        s += g_SP[((size_t)v * 1024 + i) * 64 + d];
    __shared__ float sq[4][4][64];
    __shared__ float ev[64];
    sq[q][v][d] = s;
    if (tid < 64) ev[tid] = edges_tab[tid] * 0.12f;
    __syncthreads();
    if (tid < 256) {
        float tot = sq[0][v][d] + sq[1][v][d] + sq[2][v][d] + sq[3][v][d];
        sq[0][v][d] = tot;   // own slot only; synced below before cross-reads
    }
    __syncthreads();
    if (tid < 256) {
        const float* W1 = (v == 0) ? uu_W1 : (v == 1) ? ui_W1 : (v == 2) ? ii_W1 : iu_W1;
        float u = 0.f;
        #pragma unroll
        for (int j = 0; j < 64; ++j) u += sq[0][v][j] * W1[j * 64 + d];
        g_U[v * 64 + d] = u;
    }
    if (tid >= 256 && tid < 320) {
        int dd = tid - 256;
        float nv = 0.f;
        #pragma unroll
        for (int j = 0; j < 64; ++j) nv += ev[j] * edge_W[j * 64 + dd];
        nv = nv >= 0.f ? nv : 0.01f * nv;
        g_O3[dd] = 0.5f * (nv + ev[dd]);
    }
}

// ---------------------------------------------------------------------------
// K4: final elementwise assembly of the three outputs
// ---------------------------------------------------------------------------
__global__ void __launch_bounds__(256) k4_out(float* __restrict__ out)
{
    int idx = blockIdx.x * 256 + threadIdx.x;   // 0..262143
    int r = idx >> 6, d = idx & 63;
    float x_xx   = g_S[(size_t)r * 8 + 0];
    float x_xy_x = g_S[(size_t)r * 8 + 1];
    float y_yy   = g_S[(size_t)r * 8 + 3];
    float y_yx_y = g_S[(size_t)r * 8 + 4];
    float a1 = x_xx * g_U[d];         a1 = a1 >= 0.f ? a1 : 0.01f * a1;
    float a2 = x_xy_x * g_U[64 + d];  a2 = a2 >= 0.f ? a2 : 0.01f * a2;
    float b1 = y_yy * g_U[128 + d];   b1 = b1 >= 0.f ? b1 : 0.01f * b1;
    float b2 = y_yx_y * g_U[192 + d]; b2 = b2 >= 0.f ? b2 : 0.01f * b2;
    out[idx]          = ((a1 + a2) * 0.5f + g_X[idx]) * 0.5f;
    out[262144 + idx] = ((b1 + b2) * 0.5f + g_Y[idx]) * 0.5f;
    out[524288 + idx] = g_O3[d];
}

// ---------------------------------------------------------------------------
// launch
// ---------------------------------------------------------------------------
extern "C" void kernel_launch(void* const* d_in, const int* in_sizes, int n_in,
                              void* d_out, int out_size)
{
    const int*   user_emb   = (const int*)d_in[0];
    const int*   item_emb   = (const int*)d_in[1];
    const int*   edge_emb   = (const int*)d_in[2];
    const float* gender_tab = (const float*)d_in[3];
    const float* age_tab    = (const float*)d_in[4];
    const float* occ_tab    = (const float*)d_in[5];
    const float* area_tab   = (const float*)d_in[6];
    const float* user_W     = (const float*)d_in[7];
    const float* user_b     = (const float*)d_in[8];
    const float* rate_tab   = (const float*)d_in[9];
    const float* genre_W    = (const float*)d_in[10];
    const float* director_W = (const float*)d_in[11];
    const float* actor_W    = (const float*)d_in[12];
    const float* item_W     = (const float*)d_in[13];
    const float* item_b     = (const float*)d_in[14];
    const float* edges_tab  = (const float*)d_in[15];
    const float* uu_w       = (const float*)d_in[16];
    const float* ui_w       = (const float*)d_in[17];
    const float* iu_w       = (const float*)d_in[18];
    const float* ii_w       = (const float*)d_in[19];
    const float* edge_W     = (const float*)d_in[20];
    const float* uu_W1      = (const float*)d_in[21];
    const float* ui_W1      = (const float*)d_in[22];
    const float* iu_W1      = (const float*)d_in[23];
    const float* ii_W1      = (const float*)d_in[24];
    float* out = (float*)d_out;

    k0_wt<<<KTOT, 64>>>(genre_W, director_W, actor_W, item_W);
    k0_user<<<3534, 64>>>(gender_tab, age_tab, occ_tab, area_tab, user_W, rate_tab, item_W);
    k1_gemm<<<dim3(64, NSPLIT), 256>>>(item_emb);
    k2_finalize<<<1024, 256>>>(user_emb, item_emb, edge_emb, user_b, item_b, edges_tab,
                               uu_w, ui_w, iu_w, ii_w);
    k3_reduce<<<1, 1024>>>(uu_W1, ui_W1, ii_W1, iu_W1, edge_W, edges_tab);
    k4_out<<<1024, 256>>>(out);
}

// round 6
// speedup vs baseline: 1.2636x; 1.2636x over previous
#include <cuda_runtime.h>
#include <cuda_bf16.h>
#include <cstdint>

// ---------------------------------------------------------------------------
// Problem constants
// ---------------------------------------------------------------------------
#define BSZ    4096
#define ITEMW  10242
#define KTOT   10368      // padded GEMM K: 64 (genre) + 2240 (director) + 8064 (actor)
#define NCH    162        // KTOT / 64 chunks; genre [0,1), director [1,36), actor [36,162)
#define NSLOT  5          // partial slots: 0=genre, 1=director, 2..4=actor splits
#define PC     72         // 64 numerator + count@64 + 7 pad

// ---------------------------------------------------------------------------
// Device scratch (static globals; no allocations anywhere)
// ---------------------------------------------------------------------------
__device__ __align__(16) __nv_bfloat16 g_WT[65 * KTOT];     // fused weights [d][k]; row 64 = validity
__device__ float g_UF[3528 * 64];                            // user folds
__device__ float g_RF[6 * 64];                               // rate_tab @ item_W[0:64]
__device__ float g_part[(size_t)NSLOT * BSZ * PC];           // GEMM partials
__device__ float g_X[BSZ * 64], g_Y[BSZ * 64];               // x, y vectors
__device__ float g_S[BSZ * 8];                               // per-row scalars (6 used)
__device__ float g_SP[4 * 1024 * 64];                        // per-CTA partials of s1..s4
__device__ float g_U[4 * 64];                                // u1..u4
__device__ float g_O3[64];                                   // edge-branch output row

// ---------------------------------------------------------------------------
// K0a: fold item-side weights into g_WT (bf16) + validity row.
// One CTA per 64-k chunk; item_W block and W rows cached in smem; coalesced
// bf16 output via smem transpose staging.
// ---------------------------------------------------------------------------
__global__ void __launch_bounds__(256) k0_wt(
    const float* __restrict__ genre_W, const float* __restrict__ director_W,
    const float* __restrict__ actor_W, const float* __restrict__ item_W)
{
    __shared__ float s_iw[64][65];
    __shared__ float s_w[64][65];
    int tid = threadIdx.x, d = tid & 63, q = tid >> 6;
    int blk = blockIdx.x;           // 0..161
    int kb = blk * 64;
    const float* W; int len, iwo, kr0;
    if (blk < 1)       { W = genre_W;    len = 25;   iwo = 64;  kr0 = 0;    }
    else if (blk < 36) { W = director_W; len = 2186; iwo = 128; kr0 = 64;   }
    else               { W = actor_W;    len = 8030; iwo = 192; kr0 = 2304; }

    #pragma unroll
    for (int j = q; j < 64; j += 4) s_iw[j][d] = item_W[(iwo + j) * 64 + d];
    #pragma unroll
    for (int kk = q; kk < 64; kk += 4) {
        int kr = kb + kk - kr0;
        s_w[kk][d] = (kr < len) ? W[(size_t)kr * 64 + d] : 0.f;
    }
    __syncthreads();

    float res[16];
    #pragma unroll
    for (int i = 0; i < 16; ++i) {
        int kk = q + 4 * i;
        float v = 0.f;
        #pragma unroll 16
        for (int j = 0; j < 64; ++j) v += s_w[kk][j] * s_iw[j][d];
        res[i] = v;
    }
    __syncthreads();
    #pragma unroll
    for (int i = 0; i < 16; ++i) s_w[q + 4 * i][d] = res[i];
    __syncthreads();

    // coalesced bf16 write: row d of g_WT gets 64 k-values (32 uint32)
    for (int j = tid; j < 2048; j += 256) {
        int dd = j >> 5, w = j & 31;
        __nv_bfloat162 h = __floats2bfloat162_rn(s_w[2 * w][dd], s_w[2 * w + 1][dd]);
        *(uint32_t*)&g_WT[(size_t)dd * KTOT + kb + 2 * w] = *(uint32_t*)&h;
    }
    if (tid < 64) {
        int kr = kb + tid - kr0;
        g_WT[(size_t)64 * KTOT + kb + tid] = __float2bfloat16((kr < len) ? 1.f : 0.f);
    }
}

// ---------------------------------------------------------------------------
// K0b: fold user-side tables + rate table. 32 rows per CTA; table rows staged
// in smem; area's user_W block cached in smem (covers nearly all rows).
// ---------------------------------------------------------------------------
__global__ void __launch_bounds__(256) k0_user(
    const float* __restrict__ gender_tab, const float* __restrict__ age_tab,
    const float* __restrict__ occ_tab, const float* __restrict__ area_tab,
    const float* __restrict__ user_W, const float* __restrict__ rate_tab,
    const float* __restrict__ item_W)
{
    __shared__ float s_W[64][65];
    __shared__ float s_T[32][65];
    int tid = threadIdx.x, d = tid & 63, q = tid >> 6;
    int rb = blockIdx.x * 32;

    #pragma unroll
    for (int j = q; j < 64; j += 4) s_W[j][d] = user_W[(192 + j) * 64 + d];

    for (int j2 = tid; j2 < 32 * 64; j2 += 256) {
        int rr = j2 >> 6, col = j2 & 63, r = rb + rr;
        float v = 0.f;
        if (r < 98)         v = gender_tab[r * 64 + col];
        else if (r < 105)   v = age_tab[(r - 98) * 64 + col];
        else if (r < 126)   v = occ_tab[(r - 105) * 64 + col];
        else if (r < 3528)  v = area_tab[(size_t)(r - 126) * 64 + col];
        else if (r < 3534)  v = rate_tab[(r - 3528) * 64 + col];
        s_T[rr][col] = v;
    }
    __syncthreads();

    for (int rr = q; rr < 32; rr += 4) {
        int r = rb + rr;
        if (r >= 3534) continue;
        float v = 0.f;
        if (r >= 126 && r < 3528) {
            #pragma unroll 16
            for (int j = 0; j < 64; ++j) v += s_T[rr][j] * s_W[j][d];
        } else {
            const float* Wg = (r < 98) ? user_W : (r < 105) ? (user_W + 64 * 64)
                            : (r < 126) ? (user_W + 128 * 64) : item_W;
            #pragma unroll 16
            for (int j = 0; j < 64; ++j) v += s_T[rr][j] * Wg[j * 64 + d];
        }
        if (r < 3528) g_UF[(size_t)r * 64 + d] = v;
        else          g_RF[(r - 3528) * 64 + d] = v;
    }
}

// ---------------------------------------------------------------------------
// K1: the HBM-bound bits GEMM with register-prefetch software pipeline.
// ---------------------------------------------------------------------------
#define ASTR 144   // smem row stride in bytes (64 bf16 + 8 pad)

struct Pref { int ra[8], rb[8]; uint32_t w[9]; };

__device__ __forceinline__ void k1_prefetch(const int* __restrict__ item, int rt, int c,
                                            int tid, Pref& P)
{
    int base, end;
    if (c < 1)       { base = 1;                    end = 26;    }
    else if (c < 36) { base = 26 + (c - 1) * 64;    end = 2212;  }
    else             { base = 2212 + (c - 36) * 64; end = 10242; }
    const bool full = (base + 64) <= end;

    #pragma unroll
    for (int it = 0; it < 8; ++it) {
        int idx2 = it * 512 + tid * 2;
        int row = idx2 >> 6, kk = idx2 & 63;
        int col = base + kk;
        const int* p = item + (long)(rt * 64 + row) * ITEMW + col;
        if (full) {
            int2 v = *(const int2*)p;      // 8B-aligned: base even, kk even
            P.ra[it] = v.x; P.rb[it] = v.y;
        } else {
            int v0 = 0, v1 = 0;
            if (col < end)     v0 = p[0];
            if (col + 1 < end) v1 = p[1];
            P.ra[it] = v0; P.rb[it] = v1;
        }
    }
    int kbase = c * 64;
    #pragma unroll
    for (int it = 0; it < 9; ++it) {
        int j = it * 256 + tid;
        if (j < 2080)
            P.w[it] = *(const uint32_t*)&g_WT[(size_t)(j >> 5) * KTOT + kbase + 2 * (j & 31)];
    }
}

__device__ __forceinline__ void k1_commit(const Pref& P, uint8_t* As, uint8_t* Ms, int tid)
{
    #pragma unroll
    for (int it = 0; it < 8; ++it) {
        int idx2 = it * 512 + tid * 2;
        int row = idx2 >> 6, kk = idx2 & 63;
        __nv_bfloat162 h = __floats2bfloat162_rn((float)P.ra[it], (float)P.rb[it]);
        *(uint32_t*)(As + row * ASTR + kk * 2) = *(uint32_t*)&h;
    }
    #pragma unroll
    for (int it = 0; it < 9; ++it) {
        int j = it * 256 + tid;
        if (j < 2080)
            *(uint32_t*)(Ms + (j >> 5) * ASTR + (j & 31) * 4) = P.w[it];
    }
}

__device__ __forceinline__ void k1_mma(const uint8_t* As, const uint8_t* Ms,
                                       int lane, int wm, int wg, float (&acc)[5][4])
{
    #pragma unroll
    for (int ks = 0; ks < 4; ++ks) {
        int ac = ks * 16 + 2 * (lane & 3);
        int ar = wm * 16 + (lane >> 2);
        uint32_t a0 = *(const uint32_t*)(As + ar * ASTR + ac * 2);
        uint32_t a1 = *(const uint32_t*)(As + (ar + 8) * ASTR + ac * 2);
        uint32_t a2 = *(const uint32_t*)(As + ar * ASTR + (ac + 8) * 2);
        uint32_t a3 = *(const uint32_t*)(As + (ar + 8) * ASTR + (ac + 8) * 2);
        #pragma unroll
        for (int li = 0; li < 5; ++li) {
            int l = wg + 2 * li;
            if (l < 9) {
                int br = l * 8 + (lane >> 2);
                uint32_t b0 = *(const uint32_t*)(Ms + br * ASTR + ac * 2);
                uint32_t b1 = *(const uint32_t*)(Ms + br * ASTR + (ac + 8) * 2);
                asm volatile(
                    "mma.sync.aligned.m16n8k16.row.col.f32.bf16.bf16.f32 "
                    "{%0,%1,%2,%3}, {%4,%5,%6,%7}, {%8,%9}, {%0,%1,%2,%3};\n"
                    : "+f"(acc[li][0]), "+f"(acc[li][1]), "+f"(acc[li][2]), "+f"(acc[li][3])
                    : "r"(a0), "r"(a1), "r"(a2), "r"(a3), "r"(b0), "r"(b1));
            }
        }
    }
}

__device__ __forceinline__ void k1_flush(float (&A)[5][4], int slot, int row, int tg2, int wg)
{
    float* b0 = g_part + ((size_t)slot * BSZ + row) * PC;
    float* b8 = g_part + ((size_t)slot * BSZ + row + 8) * PC;
    #pragma unroll
    for (int li = 0; li < 5; ++li) {
        int l = wg + 2 * li;
        if (l < 9) {
            int col = l * 8 + tg2;
            b0[col] = A[li][0]; b0[col + 1] = A[li][1];
            b8[col] = A[li][2]; b8[col + 1] = A[li][3];
        }
    }
}

__global__ void __launch_bounds__(256, 2) k1_gemm(const int* __restrict__ item)
{
    __shared__ __align__(16) uint8_t As[64 * ASTR];
    __shared__ __align__(16) uint8_t Ms[72 * ASTR];
    int tid = threadIdx.x, lane = tid & 31, warp = tid >> 5;
    int wm = warp & 3, wg = warp >> 2;
    int rt = blockIdx.x, sp = blockIdx.y;

    if (tid < 252) *(uint32_t*)(Ms + 65 * ASTR + tid * 4) = 0u;  // pad rows 65..71

    Pref P;
    float accA[5][4] = {}, accB[5][4] = {};

    if (sp == 0) {
        // genre (chunk 0) into accA, director (1..35) into accB
        k1_prefetch(item, rt, 0, tid, P);
        __syncthreads(); k1_commit(P, As, Ms, tid); __syncthreads();
        k1_prefetch(item, rt, 1, tid, P);
        k1_mma(As, Ms, lane, wm, wg, accA);
        for (int c = 1; c < 36; ++c) {
            __syncthreads(); k1_commit(P, As, Ms, tid); __syncthreads();
            if (c + 1 < 36) k1_prefetch(item, rt, c + 1, tid, P);
            k1_mma(As, Ms, lane, wm, wg, accB);
        }
    } else {
        int c0 = 36 + 42 * (sp - 1), c1 = c0 + 42;   // actor splits
        k1_prefetch(item, rt, c0, tid, P);
        for (int c = c0; c < c1; ++c) {
            __syncthreads(); k1_commit(P, As, Ms, tid); __syncthreads();
            if (c + 1 < c1) k1_prefetch(item, rt, c + 1, tid, P);
            k1_mma(As, Ms, lane, wm, wg, accA);
        }
    }

    int row = rt * 64 + wm * 16 + (lane >> 2);
    int tg2 = 2 * (lane & 3);
    if (sp == 0) {
        k1_flush(accA, 0, row, tg2, wg);
        k1_flush(accB, 1, row, tg2, wg);
    } else {
        k1_flush(accA, 1 + sp, row, tg2, wg);
    }
}

// ---------------------------------------------------------------------------
// K2: reduce partial slots, finalize x / y / edge, per-row scalars,
// s-vector partials. 4 rows per CTA.
// ---------------------------------------------------------------------------
__global__ void __launch_bounds__(256) k2_finalize(
    const int* __restrict__ user_emb, const int* __restrict__ item,
    const int* __restrict__ edge_emb,
    const float* __restrict__ user_b, const float* __restrict__ item_b,
    const float* __restrict__ edges_tab,
    const float* __restrict__ uu_w, const float* __restrict__ ui_w,
    const float* __restrict__ iu_w, const float* __restrict__ ii_w)
{
    int tid = threadIdx.x, lane = tid & 31, warp = tid >> 5;
    int rr = tid >> 6, d = tid & 63;
    int row = blockIdx.x * 4 + rr;

    const float* p0 = g_part + ((size_t)0 * BSZ + row) * PC;
    const float* p1 = g_part + ((size_t)1 * BSZ + row) * PC;
    const float* p2 = g_part + ((size_t)2 * BSZ + row) * PC;
    const float* p3 = g_part + ((size_t)3 * BSZ + row) * PC;
    const float* p4 = g_part + ((size_t)4 * BSZ + row) * PC;
    float ng = p0[d],              cg = p0[64];
    float nd = p1[d],              cd = p1[64];
    float na = p2[d] + p3[d] + p4[d];
    float ca = p2[64] + p3[64] + p4[64];

    int ri = item[(long)row * ITEMW];
    float y = (g_RF[ri * 64 + d] + ng / cg + nd / cd + na / ca + item_b[d]) * 0.12f;

    int gi = user_emb[row * 4 + 0], ai = user_emb[row * 4 + 1];
    int oi = user_emb[row * 4 + 2], ari = user_emb[row * 4 + 3];
    float x = (g_UF[gi * 64 + d] + g_UF[(98 + ai) * 64 + d] + g_UF[(105 + oi) * 64 + d]
             + g_UF[(size_t)(126 + ari) * 64 + d] + user_b[d]) * 0.12f;
    float e = edges_tab[edge_emb[row] * 64 + d] * 0.12f;

    g_X[row * 64 + d] = x;
    g_Y[row * 64 + d] = y;

    __shared__ float sx[4][64], sy[4][64];
    __shared__ float red[8][6], srow[4][6];
    sx[rr][d] = x; sy[rr][d] = y;

    float xe = x * e, ye = y * e;
    float pr[6] = { xe * uu_w[d], xe * ui_w[d], ye * ui_w[d],
                    ye * ii_w[d], ye * iu_w[d], xe * iu_w[d] };
    #pragma unroll
    for (int o = 16; o; o >>= 1) {
        #pragma unroll
        for (int j = 0; j < 6; ++j) pr[j] += __shfl_xor_sync(0xffffffffu, pr[j], o);
    }
    if (lane == 0) {
        #pragma unroll
        for (int j = 0; j < 6; ++j) red[warp][j] = pr[j];
    }
    __syncthreads();
    if (tid < 24) {
        int r2 = tid / 6, j = tid % 6;
        float v = red[2 * r2][j] + red[2 * r2 + 1][j];
        srow[r2][j] = v;
        g_S[(size_t)(blockIdx.x * 4 + r2) * 8 + j] = v;
    }
    __syncthreads();
    if (tid < 64) {
        float s1 = 0, s2 = 0, s3 = 0, s4 = 0;
        #pragma unroll
        for (int r2 = 0; r2 < 4; ++r2) {
            float xv = sx[r2][tid], yv = sy[r2][tid];
            s1 += srow[r2][0] * xv;   // x_xx * x
            s2 += srow[r2][2] * yv;   // x_xy_y * y
            s3 += srow[r2][3] * yv;   // y_yy * y
            s4 += srow[r2][5] * xv;   // y_yx_x * x
        }
        g_SP[(0 * 1024 + blockIdx.x) * 64 + tid] = s1;
        g_SP[(1 * 1024 + blockIdx.x) * 64 + tid] = s2;
        g_SP[(2 * 1024 + blockIdx.x) * 64 + tid] = s3;
        g_SP[(3 * 1024 + blockIdx.x) * 64 + tid] = s4;
    }
}

// ---------------------------------------------------------------------------
// K3: reduce s-vectors over 1024 CTA partials, compute u1..u4 and edge branch
// ---------------------------------------------------------------------------
__global__ void __launch_bounds__(1024) k3_reduce(
    const float* __restrict__ uu_W1, const float* __restrict__ ui_W1,
    const float* __restrict__ ii_W1, const float* __restrict__ iu_W1,
    const float* __restrict__ edge_W, const float* __restrict__ edges_tab)
{
    int tid = threadIdx.x;
    int q = tid >> 8, v = (tid >> 6) & 3, d = tid & 63;
    float s = 0.f;
    #pragma unroll 8
    for (int i = q * 256; i < q * 256 + 256; ++i)
        s += g_SP[((size_t)v * 1024 + i) * 64 + d];
    __shared__ float sq[4][4][64];
    __shared__ float ev[64];
    sq[q][v][d] = s;
    if (tid < 64) ev[tid] = edges_tab[tid] * 0.12f;
    __syncthreads();
    if (tid < 256) {
        float tot = sq[0][v][d] + sq[1][v][d] + sq[2][v][d] + sq[3][v][d];
        sq[0][v][d] = tot;
    }
    __syncthreads();
    if (tid < 256) {
        const float* W1 = (v == 0) ? uu_W1 : (v == 1) ? ui_W1 : (v == 2) ? ii_W1 : iu_W1;
        float u = 0.f;
        #pragma unroll
        for (int j = 0; j < 64; ++j) u += sq[0][v][j] * W1[j * 64 + d];
        g_U[v * 64 + d] = u;
    }
    if (tid >= 256 && tid < 320) {
        int dd = tid - 256;
        float nv = 0.f;
        #pragma unroll
        for (int j = 0; j < 64; ++j) nv += ev[j] * edge_W[j * 64 + dd];
        nv = nv >= 0.f ? nv : 0.01f * nv;
        g_O3[dd] = 0.5f * (nv + ev[dd]);
    }
}

// ---------------------------------------------------------------------------
// K4: final elementwise assembly of the three outputs
// ---------------------------------------------------------------------------
__global__ void __launch_bounds__(256) k4_out(float* __restrict__ out)
{
    int idx = blockIdx.x * 256 + threadIdx.x;   // 0..262143
    int r = idx >> 6, d = idx & 63;
    float x_xx   = g_S[(size_t)r * 8 + 0];
    float x_xy_x = g_S[(size_t)r * 8 + 1];
    float y_yy   = g_S[(size_t)r * 8 + 3];
    float y_yx_y = g_S[(size_t)r * 8 + 4];
    float a1 = x_xx * g_U[d];         a1 = a1 >= 0.f ? a1 : 0.01f * a1;
    float a2 = x_xy_x * g_U[64 + d];  a2 = a2 >= 0.f ? a2 : 0.01f * a2;
    float b1 = y_yy * g_U[128 + d];   b1 = b1 >= 0.f ? b1 : 0.01f * b1;
    float b2 = y_yx_y * g_U[192 + d]; b2 = b2 >= 0.f ? b2 : 0.01f * b2;
    out[idx]          = ((a1 + a2) * 0.5f + g_X[idx]) * 0.5f;
    out[262144 + idx] = ((b1 + b2) * 0.5f + g_Y[idx]) * 0.5f;
    out[524288 + idx] = g_O3[d];
}

// ---------------------------------------------------------------------------
// launch
// ---------------------------------------------------------------------------
extern "C" void kernel_launch(void* const* d_in, const int* in_sizes, int n_in,
                              void* d_out, int out_size)
{
    const int*   user_emb   = (const int*)d_in[0];
    const int*   item_emb   = (const int*)d_in[1];
    const int*   edge_emb   = (const int*)d_in[2];
    const float* gender_tab = (const float*)d_in[3];
    const float* age_tab    = (const float*)d_in[4];
    const float* occ_tab    = (const float*)d_in[5];
    const float* area_tab   = (const float*)d_in[6];
    const float* user_W     = (const float*)d_in[7];
    const float* user_b     = (const float*)d_in[8];
    const float* rate_tab   = (const float*)d_in[9];
    const float* genre_W    = (const float*)d_in[10];
    const float* director_W = (const float*)d_in[11];
    const float* actor_W    = (const float*)d_in[12];
    const float* item_W     = (const float*)d_in[13];
    const float* item_b     = (const float*)d_in[14];
    const float* edges_tab  = (const float*)d_in[15];
    const float* uu_w       = (const float*)d_in[16];
    const float* ui_w       = (const float*)d_in[17];
    const float* iu_w       = (const float*)d_in[18];
    const float* ii_w       = (const float*)d_in[19];
    const float* edge_W     = (const float*)d_in[20];
    const float* uu_W1      = (const float*)d_in[21];
    const float* ui_W1      = (const float*)d_in[22];
    const float* iu_W1      = (const float*)d_in[23];
    const float* ii_W1      = (const float*)d_in[24];
    float* out = (float*)d_out;

    k0_wt<<<NCH, 256>>>(genre_W, director_W, actor_W, item_W);
    k0_user<<<111, 256>>>(gender_tab, age_tab, occ_tab, area_tab, user_W, rate_tab, item_W);
    k1_gemm<<<dim3(64, 4), 256>>>(item_emb);
    k2_finalize<<<1024, 256>>>(user_emb, item_emb, edge_emb, user_b, item_b, edges_tab,
                               uu_w, ui_w, iu_w, ii_w);
    k3_reduce<<<1, 1024>>>(uu_W1, ui_W1, ii_W1, iu_W1, edge_W, edges_tab);
    k4_out<<<1024, 256>>>(out);
}

// round 7
// speedup vs baseline: 1.3400x; 1.0605x over previous
#include <cuda_runtime.h>
#include <cuda_bf16.h>
#include <cstdint>

// ---------------------------------------------------------------------------
// Problem constants
// ---------------------------------------------------------------------------
#define BSZ    4096
#define ITEMW  10242
#define KTOT   10368      // padded GEMM K: 64 (genre) + 2240 (director) + 8064 (actor)
#define NCH    162        // chunks of 64; genre [0,1), director [1,36), actor [36,162)
#define NSLOT  5          // partial slots: 0=genre, 1=director, 2..4=actor splits
#define PC     72         // 64 numerator + count@64 + 7 pad

// ---------------------------------------------------------------------------
// Device scratch (static globals; no allocations anywhere)
// ---------------------------------------------------------------------------
__device__ __align__(16) __nv_bfloat16 g_WT[65 * KTOT];     // fused weights [d][k]; row 64 = validity
__device__ float g_UF[3528 * 64];                            // user folds
__device__ float g_RF[6 * 64];                               // rate_tab @ item_W[0:64]
__device__ float g_part[(size_t)NSLOT * BSZ * PC];           // GEMM partials
__device__ float g_X[BSZ * 64], g_Y[BSZ * 64];               // x, y vectors
__device__ float g_S[BSZ * 8];                               // per-row scalars (6 used)
__device__ float g_SP[4 * 256 * 64];                         // per-CTA partials of s1..s4
__device__ float g_U[4 * 64];                                // u1..u4
__device__ float g_O3[64];                                   // edge-branch output row

// ---------------------------------------------------------------------------
// K0a: fold item-side weights into g_WT (bf16) + validity row.
// ---------------------------------------------------------------------------
__global__ void __launch_bounds__(256) k0_wt(
    const float* __restrict__ genre_W, const float* __restrict__ director_W,
    const float* __restrict__ actor_W, const float* __restrict__ item_W)
{
    __shared__ float s_iw[64][65];
    __shared__ float s_w[64][65];
    int tid = threadIdx.x, d = tid & 63, q = tid >> 6;
    int blk = blockIdx.x;           // 0..161
    int kb = blk * 64;
    const float* W; int len, iwo, kr0;
    if (blk < 1)       { W = genre_W;    len = 25;   iwo = 64;  kr0 = 0;    }
    else if (blk < 36) { W = director_W; len = 2186; iwo = 128; kr0 = 64;   }
    else               { W = actor_W;    len = 8030; iwo = 192; kr0 = 2304; }

    #pragma unroll
    for (int j = q; j < 64; j += 4) s_iw[j][d] = item_W[(iwo + j) * 64 + d];
    #pragma unroll
    for (int kk = q; kk < 64; kk += 4) {
        int kr = kb + kk - kr0;
        s_w[kk][d] = (kr < len) ? W[(size_t)kr * 64 + d] : 0.f;
    }
    __syncthreads();

    float res[16];
    #pragma unroll
    for (int i = 0; i < 16; ++i) {
        int kk = q + 4 * i;
        float v = 0.f;
        #pragma unroll 16
        for (int j = 0; j < 64; ++j) v += s_w[kk][j] * s_iw[j][d];
        res[i] = v;
    }
    __syncthreads();
    #pragma unroll
    for (int i = 0; i < 16; ++i) s_w[q + 4 * i][d] = res[i];
    __syncthreads();

    for (int j = tid; j < 2048; j += 256) {
        int dd = j >> 5, w = j & 31;
        __nv_bfloat162 h = __floats2bfloat162_rn(s_w[2 * w][dd], s_w[2 * w + 1][dd]);
        *(uint32_t*)&g_WT[(size_t)dd * KTOT + kb + 2 * w] = *(uint32_t*)&h;
    }
    if (tid < 64) {
        int kr = kb + tid - kr0;
        g_WT[(size_t)64 * KTOT + kb + tid] = __float2bfloat16((kr < len) ? 1.f : 0.f);
    }
}

// ---------------------------------------------------------------------------
// K0b: fold user-side tables + rate table.
// ---------------------------------------------------------------------------
__global__ void __launch_bounds__(256) k0_user(
    const float* __restrict__ gender_tab, const float* __restrict__ age_tab,
    const float* __restrict__ occ_tab, const float* __restrict__ area_tab,
    const float* __restrict__ user_W, const float* __restrict__ rate_tab,
    const float* __restrict__ item_W)
{
    __shared__ float s_W[64][65];
    __shared__ float s_T[32][65];
    int tid = threadIdx.x, d = tid & 63, q = tid >> 6;
    int rb = blockIdx.x * 32;

    #pragma unroll
    for (int j = q; j < 64; j += 4) s_W[j][d] = user_W[(192 + j) * 64 + d];

    for (int j2 = tid; j2 < 32 * 64; j2 += 256) {
        int rr = j2 >> 6, col = j2 & 63, r = rb + rr;
        float v = 0.f;
        if (r < 98)         v = gender_tab[r * 64 + col];
        else if (r < 105)   v = age_tab[(r - 98) * 64 + col];
        else if (r < 126)   v = occ_tab[(r - 105) * 64 + col];
        else if (r < 3528)  v = area_tab[(size_t)(r - 126) * 64 + col];
        else if (r < 3534)  v = rate_tab[(r - 3528) * 64 + col];
        s_T[rr][col] = v;
    }
    __syncthreads();

    for (int rr = q; rr < 32; rr += 4) {
        int r = rb + rr;
        if (r >= 3534) continue;
        float v = 0.f;
        if (r >= 126 && r < 3528) {
            #pragma unroll 16
            for (int j = 0; j < 64; ++j) v += s_T[rr][j] * s_W[j][d];
        } else {
            const float* Wg = (r < 98) ? user_W : (r < 105) ? (user_W + 64 * 64)
                            : (r < 126) ? (user_W + 128 * 64) : item_W;
            #pragma unroll 16
            for (int j = 0; j < 64; ++j) v += s_T[rr][j] * Wg[j * 64 + d];
        }
        if (r < 3528) g_UF[(size_t)r * 64 + d] = v;
        else          g_RF[(r - 3528) * 64 + d] = v;
    }
}

// ---------------------------------------------------------------------------
// K1: HBM-bound bits GEMM — double-buffered smem, cp.async B, 2-deep A prefetch
// ---------------------------------------------------------------------------
#define ASTR 144   // smem row stride in bytes (64 bf16 + 8 pad)

__device__ __forceinline__ void cp16(uint32_t dst, const void* src) {
    asm volatile("cp.async.cg.shared.global [%0], [%1], 16;\n" :: "r"(dst), "l"(src));
}

__device__ __forceinline__ void prefA(const int* __restrict__ item, int rt, int c,
                                      int tid, int (&R)[16])
{
    int base, end;
    if (c < 1)       { base = 1;                    end = 26;    }
    else if (c < 36) { base = 26 + (c - 1) * 64;    end = 2212;  }
    else             { base = 2212 + (c - 36) * 64; end = 10242; }
    const bool full = (base + 64) <= end;

    #pragma unroll
    for (int it = 0; it < 8; ++it) {
        int idx2 = it * 512 + tid * 2;
        int row = idx2 >> 6, kk = idx2 & 63;
        int col = base + kk;
        const int* p = item + (long)(rt * 64 + row) * ITEMW + col;
        if (full) {
            int2 v = *(const int2*)p;     // 8-B aligned (base even, kk even)
            R[2 * it] = v.x; R[2 * it + 1] = v.y;
        } else {
            R[2 * it]     = (col < end)     ? p[0] : 0;
            R[2 * it + 1] = (col + 1 < end) ? p[1] : 0;
        }
    }
}

__device__ __forceinline__ void commitA(const int (&R)[16], uint8_t* As, int tid)
{
    #pragma unroll
    for (int it = 0; it < 8; ++it) {
        int idx2 = it * 512 + tid * 2;
        int row = idx2 >> 6, kk = idx2 & 63;
        // bits are 0/1 -> exact bf16 via bit-select (1.0bf16 = 0x3F80)
        uint32_t h = (R[2 * it] ? 0x3F80u : 0u) | (R[2 * it + 1] ? 0x3F800000u : 0u);
        *(uint32_t*)(As + row * ASTR + kk * 2) = h;
    }
}

__device__ __forceinline__ void issueB(int c, uint32_t msu, int tid)
{
    const char* wt = (const char*)g_WT;
    size_t koff = (size_t)c * 128;   // kbase*2 bytes
    #pragma unroll
    for (int it = 0; it < 2; ++it) {
        int j = it * 256 + tid;
        int dd = j >> 3, w = j & 7;
        cp16(msu + dd * ASTR + w * 16, wt + (size_t)dd * (KTOT * 2) + koff + w * 16);
    }
    if (tid < 8)
        cp16(msu + 64 * ASTR + tid * 16, wt + (size_t)64 * (KTOT * 2) + koff + tid * 16);
    asm volatile("cp.async.commit_group;\n" ::: "memory");
}

__device__ __forceinline__ void k1_mma(const uint8_t* As, const uint8_t* Ms,
                                       int lane, int wm, int wg, float (&acc)[5][4])
{
    #pragma unroll
    for (int ks = 0; ks < 4; ++ks) {
        int ac = ks * 16 + 2 * (lane & 3);
        int ar = wm * 16 + (lane >> 2);
        uint32_t a0 = *(const uint32_t*)(As + ar * ASTR + ac * 2);
        uint32_t a1 = *(const uint32_t*)(As + (ar + 8) * ASTR + ac * 2);
        uint32_t a2 = *(const uint32_t*)(As + ar * ASTR + (ac + 8) * 2);
        uint32_t a3 = *(const uint32_t*)(As + (ar + 8) * ASTR + (ac + 8) * 2);
        #pragma unroll
        for (int li = 0; li < 5; ++li) {
            int l = wg + 2 * li;
            if (l < 9) {
                int br = l * 8 + (lane >> 2);
                uint32_t b0 = *(const uint32_t*)(Ms + br * ASTR + ac * 2);
                uint32_t b1 = *(const uint32_t*)(Ms + br * ASTR + (ac + 8) * 2);
                asm volatile(
                    "mma.sync.aligned.m16n8k16.row.col.f32.bf16.bf16.f32 "
                    "{%0,%1,%2,%3}, {%4,%5,%6,%7}, {%8,%9}, {%0,%1,%2,%3};\n"
                    : "+f"(acc[li][0]), "+f"(acc[li][1]), "+f"(acc[li][2]), "+f"(acc[li][3])
                    : "r"(a0), "r"(a1), "r"(a2), "r"(a3), "r"(b0), "r"(b1));
            }
        }
    }
}

__device__ __forceinline__ void k1_flush(float (&A)[5][4], int slot, int row, int tg2, int wg)
{
    float* b0 = g_part + ((size_t)slot * BSZ + row) * PC;
    float* b8 = g_part + ((size_t)slot * BSZ + row + 8) * PC;
    #pragma unroll
    for (int li = 0; li < 5; ++li) {
        int l = wg + 2 * li;
        if (l < 9) {
            int col = l * 8 + tg2;
            b0[col] = A[li][0]; b0[col + 1] = A[li][1];
            b8[col] = A[li][2]; b8[col + 1] = A[li][3];
        }
    }
}

// one pipelined chunk step: commit A(c) from regs, prefetch A(c+2), wait B(c),
// barrier, issue B(c+1), MMA(c). One __syncthreads per chunk.
#define STEP(C, S, R, ACC)                                                 \
    do {                                                                   \
        commitA(R, As[S], tid);                                            \
        if ((C) + 2 < c1) prefA(item, rt, (C) + 2, tid, R);                \
        asm volatile("cp.async.wait_group 0;\n" ::: "memory");             \
        __syncthreads();                                                   \
        if ((C) + 1 < c1) issueB((C) + 1, msu[(S) ^ 1], tid);              \
        k1_mma(As[S], Ms[S], lane, wm, wg, ACC);                           \
    } while (0)

__global__ void __launch_bounds__(256, 2) k1_gemm(const int* __restrict__ item)
{
    __shared__ __align__(16) uint8_t As[2][64 * ASTR];
    __shared__ __align__(16) uint8_t Ms[2][72 * ASTR];
    int tid = threadIdx.x, lane = tid & 31, warp = tid >> 5;
    int wm = warp & 3, wg = warp >> 2;
    int rt = blockIdx.x, sp = blockIdx.y;
    int c0, c1;
    if (sp == 0) { c0 = 0; c1 = 36; }
    else         { c0 = 36 + 42 * (sp - 1); c1 = c0 + 42; }

    // zero pad rows 65..71 of both B stages (read by l=8 fragment rows 65..71)
    if (tid < 252) {
        *(uint32_t*)(Ms[0] + 65 * ASTR + tid * 4) = 0u;
        *(uint32_t*)(Ms[1] + 65 * ASTR + tid * 4) = 0u;
    }
    uint32_t msu[2] = { (uint32_t)__cvta_generic_to_shared(Ms[0]),
                        (uint32_t)__cvta_generic_to_shared(Ms[1]) };

    float accA[5][4] = {}, accB[5][4] = {};
    int R0[16], R1[16];

    issueB(c0, msu[0], tid);
    prefA(item, rt, c0, tid, R0);
    prefA(item, rt, c0 + 1, tid, R1);

    if (sp == 0) {
        STEP(0, 0, R0, accA);        // genre
        STEP(1, 1, R1, accB);        // director...
        for (int c = 2; c < 36; c += 2) {
            STEP(c, 0, R0, accB);
            STEP(c + 1, 1, R1, accB);
        }
    } else {
        for (int c = c0; c < c1; c += 2) {
            STEP(c, 0, R0, accA);
            STEP(c + 1, 1, R1, accA);
        }
    }

    int row = rt * 64 + wm * 16 + (lane >> 2);
    int tg2 = 2 * (lane & 3);
    if (sp == 0) {
        k1_flush(accA, 0, row, tg2, wg);
        k1_flush(accB, 1, row, tg2, wg);
    } else {
        k1_flush(accA, 1 + sp, row, tg2, wg);
    }
}

// ---------------------------------------------------------------------------
// K2: reduce partial slots, finalize x / y / edge, per-row scalars,
// s-vector partials. 16 rows per CTA (4 groups of 4), 256 CTAs.
// ---------------------------------------------------------------------------
__global__ void __launch_bounds__(256) k2_finalize(
    const int* __restrict__ user_emb, const int* __restrict__ item,
    const int* __restrict__ edge_emb,
    const float* __restrict__ user_b, const float* __restrict__ item_b,
    const float* __restrict__ edges_tab,
    const float* __restrict__ uu_w, const float* __restrict__ ui_w,
    const float* __restrict__ iu_w, const float* __restrict__ ii_w)
{
    int tid = threadIdx.x, lane = tid & 31, warp = tid >> 5;
    int rr = tid >> 6, d = tid & 63;
    __shared__ float sx[4][64], sy[4][64];
    __shared__ float red[8][6], srow[4][6];
    float s1 = 0, s2 = 0, s3 = 0, s4 = 0;

    for (int g = 0; g < 4; ++g) {
        int row = blockIdx.x * 16 + g * 4 + rr;

        const float* p0 = g_part + ((size_t)0 * BSZ + row) * PC;
        const float* p1 = g_part + ((size_t)1 * BSZ + row) * PC;
        const float* p2 = g_part + ((size_t)2 * BSZ + row) * PC;
        const float* p3 = g_part + ((size_t)3 * BSZ + row) * PC;
        const float* p4 = g_part + ((size_t)4 * BSZ + row) * PC;
        float ng = p0[d],              cg = p0[64];
        float nd = p1[d],              cd = p1[64];
        float na = p2[d] + p3[d] + p4[d];
        float ca = p2[64] + p3[64] + p4[64];

        int ri = item[(long)row * ITEMW];
        float y = (g_RF[ri * 64 + d] + ng / cg + nd / cd + na / ca + item_b[d]) * 0.12f;

        int gi = user_emb[row * 4 + 0], ai = user_emb[row * 4 + 1];
        int oi = user_emb[row * 4 + 2], ari = user_emb[row * 4 + 3];
        float x = (g_UF[gi * 64 + d] + g_UF[(98 + ai) * 64 + d] + g_UF[(105 + oi) * 64 + d]
                 + g_UF[(size_t)(126 + ari) * 64 + d] + user_b[d]) * 0.12f;
        float e = edges_tab[edge_emb[row] * 64 + d] * 0.12f;

        g_X[row * 64 + d] = x;
        g_Y[row * 64 + d] = y;

        __syncthreads();                // smem reuse guard from previous group
        sx[rr][d] = x; sy[rr][d] = y;

        float xe = x * e, ye = y * e;
        float pr[6] = { xe * uu_w[d], xe * ui_w[d], ye * ui_w[d],
                        ye * ii_w[d], ye * iu_w[d], xe * iu_w[d] };
        #pragma unroll
        for (int o = 16; o; o >>= 1) {
            #pragma unroll
            for (int j = 0; j < 6; ++j) pr[j] += __shfl_xor_sync(0xffffffffu, pr[j], o);
        }
        if (lane == 0) {
            #pragma unroll
            for (int j = 0; j < 6; ++j) red[warp][j] = pr[j];
        }
        __syncthreads();
        if (tid < 24) {
            int r2 = tid / 6, j = tid % 6;
            float v = red[2 * r2][j] + red[2 * r2 + 1][j];
            srow[r2][j] = v;
            g_S[(size_t)(blockIdx.x * 16 + g * 4 + r2) * 8 + j] = v;
        }
        __syncthreads();
        if (tid < 64) {
            #pragma unroll
            for (int r2 = 0; r2 < 4; ++r2) {
                float xv = sx[r2][tid], yv = sy[r2][tid];
                s1 += srow[r2][0] * xv;   // x_xx * x
                s2 += srow[r2][2] * yv;   // x_xy_y * y
                s3 += srow[r2][3] * yv;   // y_yy * y
                s4 += srow[r2][5] * xv;   // y_yx_x * x
            }
        }
    }
    if (tid < 64) {
        g_SP[(0 * 256 + blockIdx.x) * 64 + tid] = s1;
        g_SP[(1 * 256 + blockIdx.x) * 64 + tid] = s2;
        g_SP[(2 * 256 + blockIdx.x) * 64 + tid] = s3;
        g_SP[(3 * 256 + blockIdx.x) * 64 + tid] = s4;
    }
}

// ---------------------------------------------------------------------------
// K3: reduce s-vectors over 256 CTA partials, compute u1..u4 and edge branch
// ---------------------------------------------------------------------------
__global__ void __launch_bounds__(1024) k3_reduce(
    const float* __restrict__ uu_W1, const float* __restrict__ ui_W1,
    const float* __restrict__ ii_W1, const float* __restrict__ iu_W1,
    const float* __restrict__ edge_W, const float* __restrict__ edges_tab)
{
    int tid = threadIdx.x;
    int q = tid >> 8, v = (tid >> 6) & 3, d = tid & 63;
    float s = 0.f;
    #pragma unroll 8
    for (int i = q * 64; i < q * 64 + 64; ++i)
        s += g_SP[((size_t)v * 256 + i) * 64 + d];
    __shared__ float sq[4][4][64];
    __shared__ float ev[64];
    sq[q][v][d] = s;
    if (tid < 64) ev[tid] = edges_tab[tid] * 0.12f;
    __syncthreads();
    if (tid < 256) {
        float tot = sq[0][v][d] + sq[1][v][d] + sq[2][v][d] + sq[3][v][d];
        sq[0][v][d] = tot;
    }
    __syncthreads();
    if (tid < 256) {
        const float* W1 = (v == 0) ? uu_W1 : (v == 1) ? ui_W1 : (v == 2) ? ii_W1 : iu_W1;
        float u = 0.f;
        #pragma unroll
        for (int j = 0; j < 64; ++j) u += sq[0][v][j] * W1[j * 64 + d];
        g_U[v * 64 + d] = u;
    }
    if (tid >= 256 && tid < 320) {
        int dd = tid - 256;
        float nv = 0.f;
        #pragma unroll
        for (int j = 0; j < 64; ++j) nv += ev[j] * edge_W[j * 64 + dd];
        nv = nv >= 0.f ? nv : 0.01f * nv;
        g_O3[dd] = 0.5f * (nv + ev[dd]);
    }
}

// ---------------------------------------------------------------------------
// K4: final elementwise assembly of the three outputs
// ---------------------------------------------------------------------------
__global__ void __launch_bounds__(256) k4_out(float* __restrict__ out)
{
    int idx = blockIdx.x * 256 + threadIdx.x;   // 0..262143
    int r = idx >> 6, d = idx & 63;
    float x_xx   = g_S[(size_t)r * 8 + 0];
    float x_xy_x = g_S[(size_t)r * 8 + 1];
    float y_yy   = g_S[(size_t)r * 8 + 3];
    float y_yx_y = g_S[(size_t)r * 8 + 4];
    float a1 = x_xx * g_U[d];         a1 = a1 >= 0.f ? a1 : 0.01f * a1;
    float a2 = x_xy_x * g_U[64 + d];  a2 = a2 >= 0.f ? a2 : 0.01f * a2;
    float b1 = y_yy * g_U[128 + d];   b1 = b1 >= 0.f ? b1 : 0.01f * b1;
    float b2 = y_yx_y * g_U[192 + d]; b2 = b2 >= 0.f ? b2 : 0.01f * b2;
    out[idx]          = ((a1 + a2) * 0.5f + g_X[idx]) * 0.5f;
    out[262144 + idx] = ((b1 + b2) * 0.5f + g_Y[idx]) * 0.5f;
    out[524288 + idx] = g_O3[d];
}

// ---------------------------------------------------------------------------
// launch
// ---------------------------------------------------------------------------
extern "C" void kernel_launch(void* const* d_in, const int* in_sizes, int n_in,
                              void* d_out, int out_size)
{
    const int*   user_emb   = (const int*)d_in[0];
    const int*   item_emb   = (const int*)d_in[1];
    const int*   edge_emb   = (const int*)d_in[2];
    const float* gender_tab = (const float*)d_in[3];
    const float* age_tab    = (const float*)d_in[4];
    const float* occ_tab    = (const float*)d_in[5];
    const float* area_tab   = (const float*)d_in[6];
    const float* user_W     = (const float*)d_in[7];
    const float* user_b     = (const float*)d_in[8];
    const float* rate_tab   = (const float*)d_in[9];
    const float* genre_W    = (const float*)d_in[10];
    const float* director_W = (const float*)d_in[11];
    const float* actor_W    = (const float*)d_in[12];
    const float* item_W     = (const float*)d_in[13];
    const float* item_b     = (const float*)d_in[14];
    const float* edges_tab  = (const float*)d_in[15];
    const float* uu_w       = (const float*)d_in[16];
    const float* ui_w       = (const float*)d_in[17];
    const float* iu_w       = (const float*)d_in[18];
    const float* ii_w       = (const float*)d_in[19];
    const float* edge_W     = (const float*)d_in[20];
    const float* uu_W1      = (const float*)d_in[21];
    const float* ui_W1      = (const float*)d_in[22];
    const float* iu_W1      = (const float*)d_in[23];
    const float* ii_W1      = (const float*)d_in[24];
    float* out = (float*)d_out;

    k0_wt<<<NCH, 256>>>(genre_W, director_W, actor_W, item_W);
    k0_user<<<111, 256>>>(gender_tab, age_tab, occ_tab, area_tab, user_W, rate_tab, item_W);
    k1_gemm<<<dim3(64, 4), 256>>>(item_emb);
    k2_finalize<<<256, 256>>>(user_emb, item_emb, edge_emb, user_b, item_b, edges_tab,
                              uu_w, ui_w, iu_w, ii_w);
    k3_reduce<<<1, 1024>>>(uu_W1, ui_W1, ii_W1, iu_W1, edge_W, edges_tab);
    k4_out<<<1024, 256>>>(out);
}